// round 5
// baseline (speedup 1.0000x reference)
#include <cuda_runtime.h>
#include <cstdint>

// ---------------- problem constants ----------------
#define TOTAL   340704u        // 16224 + 64896 + 259584 candidates
#define OFF1    16224u
#define OFF2    81120u
#define KSEL    512u
#define NBOX    1536
#define NWORD   24             // 1536/64 mask words per row
#define BINBASE 0xBF199u       // (bits(0.6)|sign)>>12 ; keys for obj in (0.6,1]
#define NBIN    1640u          // 0xBF800 - 0xBF199 + 1
#define NBINP   1664u          // padded
#define POOLCAP 65536u
#define SORTCAP 4096

typedef unsigned long long u64;
typedef uint32_t u32;

// ---------------- device scratch (static, allocation-free) ----------------
// Zero-initialized at module load; the final tail re-zeroes everything it
// consumed, so every run starts from identical state (deterministic).
__device__ u32   g_hist[3*NBINP];
__device__ u32   g_validCount[3];
__device__ int   g_binB[3];
__device__ u32   g_selCount[3];
__device__ u32   g_poolCount[3];
__device__ u64   g_sel[3*512];
__device__ u64   g_pool[3*POOLCAP];
__device__ u64   g_sorted[NBOX];
__device__ float g_boxes[NBOX*9];
__device__ float g_nmsb[NBOX*5];     // x1,y1,x2,y2,area
__device__ int   g_valid[NBOX];
__device__ u64   g_mask[NBOX*NWORD];
__device__ u32   g_done_hist, g_done_sel, g_done_mask;

// ---------------- shared address/key computation ----------------
__device__ __forceinline__ void cand_addr(u32 i,
        const float* __restrict__ o13, const float* __restrict__ o26,
        const float* __restrict__ o52,
        float& x, int& s, u32& orig) {
    if (i < OFF1) {                 // H=13, HW=169, NHW=5408
        u32 loc = i;
        u32 a = loc / 5408u, r = loc - a*5408u;
        u32 n = r / 169u,  hw = r - n*169u;
        x = o13[(n*255u + a*85u)*169u + hw]; s = 0; orig = r*3u + a;
    } else if (i < OFF2) {          // H=26, HW=676, NHW=21632
        u32 loc = i - OFF1;
        u32 a = loc / 21632u, r = loc - a*21632u;
        u32 n = r / 676u,  hw = r - n*676u;
        x = o26[(n*255u + a*85u)*676u + hw]; s = 1; orig = r*3u + a;
    } else {                        // H=52, HW=2704, NHW=86528
        u32 loc = i - OFF2;
        u32 a = loc / 86528u, r = loc - a*86528u;
        u32 n = r / 2704u, hw = r - n*2704u;
        x = o52[(n*255u + a*85u)*2704u + hw]; s = 2; orig = r*3u + a;
    }
}

// ---------------- K1: histogram + (tail) threshold-bin scan ----------------
__global__ __launch_bounds__(1024) void k_hist(const float* __restrict__ o13,
                                               const float* __restrict__ o26,
                                               const float* __restrict__ o52) {
    __shared__ u32 sh[3*NBINP];
    __shared__ u32 svc[3];
    __shared__ u32 isLast;
    const u32 t = threadIdx.x;
    for (u32 b = t; b < 3u*NBINP; b += 1024u) sh[b] = 0u;
    if (t < 3u) svc[t] = 0u;
    __syncthreads();
    for (u32 i = blockIdx.x*1024u + t; i < TOTAL; i += 65536u) {
        float x; int s; u32 orig;
        cand_addr(i, o13, o26, o52, x, s, orig);
        float obj = 1.f / (1.f + expf(-x));
        if (obj > 0.6f) {
            u32 key = __float_as_uint(obj) | 0x80000000u;
            atomicAdd(&sh[(u32)s*NBINP + ((key >> 12) - BINBASE)], 1u);
            atomicAdd(&svc[s], 1u);
        }
    }
    __syncthreads();
    for (u32 b = t; b < 3u*NBINP; b += 1024u) {
        u32 v = sh[b];
        if (v) atomicAdd(&g_hist[b], v);
    }
    if (t < 3u && svc[t]) atomicAdd(&g_validCount[t], svc[t]);
    __threadfence();
    __syncthreads();
    if (t == 0) isLast = (atomicAdd(&g_done_hist, 1u) == gridDim.x - 1u);
    __syncthreads();
    if (!isLast) return;

    // ---- tail: per-scale threshold bin via suffix scan (1024 threads) ----
    u32* ss = sh;                       // reuse smem
    for (int s = 0; s < 3; s++) {
        __syncthreads();
        if (g_validCount[s] < KSEL) { if (t == 0) g_binB[s] = -2; continue; }
        const u32* hist = g_hist + (u32)s*NBINP;
        u32 b0 = t*2u;
        u32 part = 0u;
        if (b0     < NBIN) part += hist[b0];
        if (b0 + 1 < NBIN) part += hist[b0 + 1];
        ss[t] = part;
        __syncthreads();
        for (u32 off = 1; off < 1024u; off <<= 1) {   // inclusive suffix scan
            u32 add = (t + off < 1024u) ? ss[t + off] : 0u;
            __syncthreads();
            ss[t] += add;
            __syncthreads();
        }
        u32 S = ss[t];
        u32 Sn = (t < 1023u) ? ss[t + 1] : 0u;
        if (S >= KSEL && Sn < KSEL) {
            u32 cum = Sn;
            for (int k = 1; k >= 0; k--) {
                u32 b = b0 + (u32)k;
                if (b < NBIN) {
                    u32 c = hist[b];
                    cum += c;
                    if (cum >= KSEL) { g_binB[s] = (int)b; break; }
                }
            }
        }
    }
    if (t == 0) g_done_hist = 0u;       // reset for next run
}

// ---------------- K2: select + (tail) top-off & global bitonic sort ----------------
__global__ __launch_bounds__(1024) void k_select(const float* __restrict__ o13,
                                                 const float* __restrict__ o26,
                                                 const float* __restrict__ o52) {
    __shared__ __align__(16) u64 sm[SORTCAP];    // 32 KB (tail only)
    __shared__ u32 sTot[3];
    __shared__ u32 scnt, srank;
    __shared__ u32 isLast;
    const u32 t = threadIdx.x;
    const int b0 = g_binB[0], b1 = g_binB[1], b2 = g_binB[2];
    for (u32 i = blockIdx.x*1024u + t; i < TOTAL; i += 65536u) {
        float x; int s; u32 orig;
        cand_addr(i, o13, o26, o52, x, s, orig);
        float obj = 1.f / (1.f + expf(-x));
        if (!(obj > 0.6f)) continue;
        u32 key = __float_as_uint(obj) | 0x80000000u;
        int hidx = (int)((key >> 12) - BINBASE);
        int tb = (s == 0) ? b0 : (s == 1) ? b1 : b2;
        if (hidx > tb) {
            u32 pos = atomicAdd(&g_selCount[s], 1u);
            g_sel[(u32)s*512u + pos] = ((u64)key << 32) | orig;
        } else if (hidx == tb) {
            u32 pos = atomicAdd(&g_poolCount[s], 1u);
            if (pos < POOLCAP)
                g_pool[(u32)s*POOLCAP + pos] = ((u64)key << 32) | (u32)(~orig);
        }
    }
    __threadfence();
    __syncthreads();
    if (t == 0) isLast = (atomicAdd(&g_done_sel, 1u) == gridDim.x - 1u);
    __syncthreads();
    if (!isLast) return;

    // ---- tail: threshold-bin top-off + global 2048 bitonic sort ----
    for (int s = 0; s < 3; s++) {
        u32 direct = g_selCount[s];
        u32 valid  = g_validCount[s];
        u32 need   = (valid >= KSEL) ? (KSEL - direct) : 0u;
        if (t == 0) sTot[s] = direct + need;
        u32 n = g_poolCount[s]; if (n > POOLCAP) n = POOLCAP;
        if (need > 0u) {
            if (n <= (u32)SORTCAP) {
                u32 P = 2u; while (P < n) P <<= 1u;
                for (u32 i = t; i < P; i += 1024u)
                    sm[i] = (i < n) ? g_pool[(u32)s*POOLCAP + i] : 0ull;
                __syncthreads();
                for (u32 k = 2; k <= P; k <<= 1)
                    for (u32 j = k >> 1; j > 0; j >>= 1) {
                        for (u32 i = t; i < P; i += 1024u) {
                            u32 ixj = i ^ j;
                            if (ixj > i) {
                                bool desc = ((i & k) == 0u);
                                u64 x = sm[i], y = sm[ixj];
                                if (desc ? (x < y) : (x > y)) { sm[i] = y; sm[ixj] = x; }
                            }
                        }
                        __syncthreads();
                    }
                for (u32 j = t; j < need; j += 1024u) {
                    u64 v = sm[j];
                    g_sel[(u32)s*512u + direct + j] =
                        (v & 0xFFFFFFFF00000000ull) | (u32)(~(u32)v);
                }
            } else {
                // fallback: exact selection via 64-bit binary search (v unique)
                u64 lo = 1ull, hi = 0xFFFFFFFFFFFFFFFFull;
                while (lo < hi) {
                    u64 mid = lo + ((hi - lo + 1ull) >> 1);
                    if (t == 0) scnt = 0u;
                    __syncthreads();
                    u32 c = 0u;
                    for (u32 j = t; j < n; j += 1024u)
                        if (g_pool[(u32)s*POOLCAP + j] >= mid) c++;
                    if (c) atomicAdd(&scnt, c);
                    __syncthreads();
                    u32 total = scnt;
                    __syncthreads();
                    if (total >= need) lo = mid; else hi = mid - 1ull;
                }
                if (t == 0) srank = 0u;
                __syncthreads();
                for (u32 j = t; j < n; j += 1024u) {
                    u64 v = g_pool[(u32)s*POOLCAP + j];
                    if (v >= lo) {
                        u32 p = atomicAdd(&srank, 1u);
                        if (p < need)
                            g_sel[(u32)s*512u + direct + p] =
                                (v & 0xFFFFFFFF00000000ull) | (u32)(~(u32)v);
                    }
                }
            }
        }
        __syncthreads();
    }
    const u32 offc[3] = {0u, OFF1, OFF2};
    for (u32 j = t; j < 2048u; j += 1024u) {
        u64 v = 0ull;
        if (j < (u32)NBOX) {
            u32 s = j >> 9, p = j & 511u;
            if (p < sTot[s]) {
                u64 e = g_sel[s*512u + p];
                u32 key  = (u32)(e >> 32);
                u32 gidx = offc[s] + (u32)e;
                v = ((u64)key << 32) | (u32)(~gidx);
            }
        }
        sm[j] = v;
    }
    __syncthreads();
    for (u32 k = 2; k <= 2048u; k <<= 1)
        for (u32 j = k >> 1; j > 0; j >>= 1) {
            for (u32 i = t; i < 2048u; i += 1024u) {
                u32 ixj = i ^ j;
                if (ixj > i) {
                    bool desc = ((i & k) == 0u);
                    u64 x = sm[i], y = sm[ixj];
                    if (desc ? (x < y) : (x > y)) { sm[i] = y; sm[ixj] = x; }
                }
            }
            __syncthreads();
        }
    for (u32 j = t; j < (u32)NBOX; j += 1024u) g_sorted[j] = sm[j];
    if (t == 0) g_done_sel = 0u;        // reset for next run
}

// ---------------- K3: decode winners (one warp per box) ----------------
__global__ void k_decode(const float* __restrict__ o13, const float* __restrict__ o26,
                         const float* __restrict__ o52,
                         const float* __restrict__ a13, const float* __restrict__ a26,
                         const float* __restrict__ a52) {
    int r = (blockIdx.x * blockDim.x + threadIdx.x) >> 5;
    int lane = threadIdx.x & 31;
    if (r >= NBOX) return;
    u64 e = g_sorted[r];
    u32 key = (u32)(e >> 32);
    if (key == 0u) {
        if (lane == 0) {
            #pragma unroll
            for (int k = 0; k < 9; k++) g_boxes[r*9+k] = 0.f;
            #pragma unroll
            for (int k = 0; k < 5; k++) g_nmsb[r*5+k] = 0.f;
            g_valid[r] = 0;
        }
        return;
    }
    u32 gidx = ~(u32)e;
    const float* p; const float* anc; int H; float ts; u32 loc;
    if (gidx < OFF1)      { p=o13; anc=a13; H=13; ts=32.f; loc=gidx; }
    else if (gidx < OFF2) { p=o26; anc=a26; H=26; ts=16.f; loc=gidx-OFF1; }
    else                  { p=o52; anc=a52; H=52; ts=8.f;  loc=gidx-OFF2; }
    u32 a = loc % 3u; u32 q = loc / 3u;
    u32 w = q % (u32)H; q /= (u32)H;
    u32 h = q % (u32)H; u32 n = q / (u32)H;
    int HW = H*H;
    const float* base = p + (size_t)(n*255u + a*85u)*HW + h*H + w;
    // lanes 1..4 fetch box deltas in parallel with the class loads
    float aux = 0.f;
    if (lane >= 1 && lane <= 4) aux = base[lane * HW];
    float bv = -1e30f; int bc = 1 << 30;       // argmax 80 classes, first-max
    for (int c = lane; c < 80; c += 32) {
        float v = base[(5 + c) * HW];
        if (v > bv) { bv = v; bc = c; }
    }
    #pragma unroll
    for (int off = 16; off; off >>= 1) {
        float ov = __shfl_down_sync(0xffffffffu, bv, off);
        int   oc = __shfl_down_sync(0xffffffffu, bc, off);
        if (ov > bv || (ov == bv && oc < bc)) { bv = ov; bc = oc; }
    }
    float v1 = __shfl_sync(0xffffffffu, aux, 1);
    float v2 = __shfl_sync(0xffffffffu, aux, 2);
    float v3 = __shfl_sync(0xffffffffu, aux, 3);
    float v4 = __shfl_sync(0xffffffffu, aux, 4);
    if (lane == 0) {
        float obj = __uint_as_float(key ^ 0x80000000u);
        float cx = ((float)w + v1) * ts / 416.0f;
        float cy = ((float)h + v2) * ts / 416.0f;
        float bw = anc[a*2+0] * expf(v3) / 416.0f;
        float bh = anc[a*2+1] * expf(v4) / 416.0f;
        float* B = &g_boxes[r*9];
        B[0]=(float)n; B[1]=cx; B[2]=cy; B[3]=bw; B[4]=bh;
        B[5]=obj; B[6]=(float)bc; B[7]=(float)h; B[8]=(float)w;
        float x1 = cx - bw*0.5f, y1 = cy - bh*0.5f;
        float x2 = cx + bw*0.5f, y2 = cy + bh*0.5f;
        float area = fmaxf(x2-x1, 0.f) * fmaxf(y2-y1, 0.f);
        float* Nn = &g_nmsb[r*5];
        Nn[0]=x1; Nn[1]=y1; Nn[2]=x2; Nn[3]=y2; Nn[4]=area;
        g_valid[r] = 1;
    }
}

// ---------------- K4: IoU bitmask + (tail) greedy scan + output + re-zero ----------------
// 48 blocks x 256 threads; each block covers 32 rows x 24 column-words with a
// warp-uniform cw mapping (all smem column reads are broadcasts).
__global__ __launch_bounds__(256) void k_mask_nms(float* __restrict__ out) {
    __shared__ __align__(16) unsigned char shbuf[30720];   // boxes / NMS tiles
    __shared__ u64 svalidw[NWORD];
    __shared__ u64 skeep[NWORD];
    __shared__ u32 isLast;
    const int tid = threadIdx.x;
    float* sb = (float*)shbuf;                 // 1536*5 floats = 30720 B
    for (int i = tid; i < NBOX*5; i += 256) sb[i] = g_nmsb[i];
    __syncthreads();
    const int rbase = blockIdx.x * 32;
    for (int task = tid; task < 32*NWORD; task += 256) {
        int cw = task >> 5;                    // warp-uniform
        int r  = rbase + (task & 31);
        float x1 = sb[r*5+0], y1 = sb[r*5+1], x2 = sb[r*5+2],
              y2 = sb[r*5+3], ar = sb[r*5+4];
        u64 bits = 0ull;
        int cbase = cw * 64;
        #pragma unroll 4
        for (int j = 0; j < 64; j++) {
            int cc = cbase + j;
            if (cc > r) {
                const float* c = &sb[cc*5];
                float ix = fmaxf(fminf(x2, c[2]) - fmaxf(x1, c[0]), 0.f);
                float iy = fmaxf(fminf(y2, c[3]) - fmaxf(y1, c[1]), 0.f);
                float iou = (ix * iy) / fmaxf(fminf(ar, c[4]), 1e-9f);
                if (iou > 0.7f) bits |= (1ull << j);
            }
        }
        g_mask[r*NWORD + cw] = bits;
    }
    __threadfence();
    __syncthreads();
    if (tid == 0) isLast = (atomicAdd(&g_done_mask, 1u) == gridDim.x - 1u);
    __syncthreads();
    if (!isLast) return;

    // ---- tail: greedy serial scan (register closure) + masked output ----
    u64* tile0 = (u64*)shbuf;                  // 2 x 12288 B, aliases sb
    u64* tile1 = (u64*)(shbuf + 12288);
    if (tid < NWORD) {
        u64 v = 0ull;
        for (int j = 0; j < 64; j++) if (g_valid[tid*64 + j]) v |= 1ull << j;
        svalidw[tid] = v;
    }
    __syncthreads();                           // sb no longer needed
    for (int k = tid; k < 64*NWORD; k += 256) tile0[k] = g_mask[k];
    __syncthreads();
    u64 remv = 0ull;                           // lane w (w<NWORD) holds word w
    for (int c = 0; c < NWORD; c++) {
        u64* T = (c & 1) ? tile1 : tile0;
        u64* Tn = (c & 1) ? tile0 : tile1;
        if (tid >= 32 && c + 1 < NWORD) {      // prefetch next chunk
            for (int k = tid - 32; k < 64*NWORD; k += 224)
                Tn[k] = g_mask[(size_t)(c+1)*(64*NWORD) + k];
        }
        if (tid < 32) {
            u64 cur = __shfl_sync(0xffffffffu, remv, c);
            u64 keptbits = 0ull;
            if (tid == 0) {
                u64 validw = svalidw[c];
                u64 rows[64];
                #pragma unroll
                for (int j = 0; j < 64; j++) rows[j] = T[j*NWORD + c];
                #pragma unroll
                for (int j = 0; j < 64; j++) {
                    u64 b = 1ull << j;
                    if ((validw & b) && !(cur & b)) { cur |= rows[j]; keptbits |= b; }
                }
                skeep[c] = keptbits;
            }
            keptbits = __shfl_sync(0xffffffffu, keptbits, 0);
            if (tid < NWORD) {
                u64 kb = keptbits, acc = 0ull;
                while (kb) {
                    int j = __ffsll((long long)kb) - 1;
                    kb &= kb - 1ull;
                    acc |= T[j*NWORD + tid];
                }
                remv |= acc;
            }
        }
        __syncthreads();
    }
    for (int e = tid; e < NBOX*9; e += 256) {
        int r = e / 9;
        out[e] = g_boxes[e] * (((skeep[r >> 6] >> (r & 63)) & 1ull) ? 1.f : 0.f);
    }
    // ---- re-zero selection state for the next run ----
    for (u32 z = tid; z < 3u*NBINP; z += 256u) g_hist[z] = 0u;
    if (tid < 3) { g_validCount[tid] = 0u; g_selCount[tid] = 0u; g_poolCount[tid] = 0u; }
    if (tid == 0) g_done_mask = 0u;
}

// ---------------- launcher: 4 graph nodes ----------------
extern "C" void kernel_launch(void* const* d_in, const int* in_sizes, int n_in,
                              void* d_out, int out_size) {
    const float* o13 = (const float*)d_in[0];
    const float* o26 = (const float*)d_in[1];
    const float* o52 = (const float*)d_in[2];
    const float* a13 = (const float*)d_in[3];
    const float* a26 = (const float*)d_in[4];
    const float* a52 = (const float*)d_in[5];
    float* out = (float*)d_out;

    k_hist    <<<64, 1024>>>(o13, o26, o52);
    k_select  <<<64, 1024>>>(o13, o26, o52);
    k_decode  <<<192, 256>>>(o13, o26, o52, a13, a26, a52);
    k_mask_nms<<<48, 256>>>(out);
    (void)in_sizes; (void)n_in; (void)out_size;
}

// round 6
// speedup vs baseline: 1.2142x; 1.2142x over previous
#include <cuda_runtime.h>
#include <cstdint>

// ---------------- problem constants ----------------
#define TOTAL   340704u        // 16224 + 64896 + 259584 candidates
#define OFF1    16224u
#define OFF2    81120u
#define KSEL    512u
#define NBOX    1536
#define NWORD   24             // 1536/64 mask words per row
#define BINBASE 0xBF199u       // (bits(0.6)|sign)>>12 ; keys for obj in (0.6,1]
#define NBIN    1640u          // 0xBF800 - 0xBF199 + 1
#define NBINP   1664u          // padded
#define POOLCAP 65536u
#define SORTCAP 4096

typedef unsigned long long u64;
typedef uint32_t u32;

// ---------------- device scratch (static, allocation-free) ----------------
// NOTE: zero-initialized at module load; k_nms_out re-zeroes at the end of
// every run, so every execution starts from zeroed state (deterministic).
__device__ u32   g_hist[3*NBINP];
__device__ u32   g_validCount[3];
__device__ u32   g_selCount[3];
__device__ u32   g_poolCount[3];
__device__ u64   g_sel[3*512];
__device__ u64   g_pool[3*POOLCAP];
__device__ u64   g_sorted[NBOX];
__device__ float g_boxes[NBOX*9];
__device__ float g_nmsb[NBOX*5];     // x1,y1,x2,y2,area
__device__ int   g_valid[NBOX];
__device__ u64   g_mask[NBOX*NWORD];

// ---------------- shared address/key computation ----------------
__device__ __forceinline__ void cand_addr(u32 i,
        const float* __restrict__ o13, const float* __restrict__ o26,
        const float* __restrict__ o52,
        float& x, int& s, u32& orig) {
    if (i < OFF1) {                 // H=13, HW=169, NHW=5408
        u32 loc = i;
        u32 a = loc / 5408u, r = loc - a*5408u;
        u32 n = r / 169u,  hw = r - n*169u;
        x = o13[(n*255u + a*85u)*169u + hw]; s = 0; orig = r*3u + a;
    } else if (i < OFF2) {          // H=26, HW=676, NHW=21632
        u32 loc = i - OFF1;
        u32 a = loc / 21632u, r = loc - a*21632u;
        u32 n = r / 676u,  hw = r - n*676u;
        x = o26[(n*255u + a*85u)*676u + hw]; s = 1; orig = r*3u + a;
    } else {                        // H=52, HW=2704, NHW=86528
        u32 loc = i - OFF2;
        u32 a = loc / 86528u, r = loc - a*86528u;
        u32 n = r / 2704u, hw = r - n*2704u;
        x = o52[(n*255u + a*85u)*2704u + hw]; s = 2; orig = r*3u + a;
    }
}

// ---------------- K1: 1640-bin histogram of score keys ----------------
__global__ __launch_bounds__(256) void k_hist(const float* __restrict__ o13,
                                              const float* __restrict__ o26,
                                              const float* __restrict__ o52) {
    __shared__ u32 sh[3*NBINP];
    __shared__ u32 svc[3];
    for (u32 b = threadIdx.x; b < 3u*NBINP; b += 256u) sh[b] = 0u;
    if (threadIdx.x < 3u) svc[threadIdx.x] = 0u;
    __syncthreads();
    for (u32 i = blockIdx.x*256u + threadIdx.x; i < TOTAL; i += 65536u) {
        float x; int s; u32 orig;
        cand_addr(i, o13, o26, o52, x, s, orig);
        float obj = 1.f / (1.f + expf(-x));
        if (obj > 0.6f) {
            u32 key = __float_as_uint(obj) | 0x80000000u;
            atomicAdd(&sh[(u32)s*NBINP + ((key >> 12) - BINBASE)], 1u);
            atomicAdd(&svc[s], 1u);
        }
    }
    __syncthreads();
    for (u32 b = threadIdx.x; b < 3u*NBINP; b += 256u) {
        u32 v = sh[b];
        if (v) atomicAdd(&g_hist[b], v);
    }
    if (threadIdx.x < 3u && svc[threadIdx.x]) atomicAdd(&g_validCount[threadIdx.x], svc[threadIdx.x]);
}

// ---------------- K2: recompute keys; direct-select above threshold bin,
//                  pool the threshold bin. Threshold bin found per block
//                  by a redundant in-smem suffix scan of the global hist. ----
__global__ __launch_bounds__(256) void k_select(const float* __restrict__ o13,
                                                const float* __restrict__ o26,
                                                const float* __restrict__ o52) {
    __shared__ u32 ss[256];
    __shared__ int shBin[3];
    const u32 t = threadIdx.x;
    // per-scale threshold-bin scan (block-redundant, uniform branches)
    for (int s = 0; s < 3; s++) {
        if (g_validCount[s] < KSEL) {
            if (t == 0) shBin[s] = -2;            // select every valid directly
        } else {
            u32 b0 = t * 7u;
            u32 part = 0u;
            #pragma unroll
            for (u32 k = 0; k < 7u; k++) {
                u32 b = b0 + k;
                if (b < NBIN) part += g_hist[(u32)s*NBINP + b];
            }
            ss[t] = part;
            __syncthreads();
            for (u32 off = 1; off < 256u; off <<= 1) {   // inclusive suffix scan
                u32 add = (t + off < 256u) ? ss[t + off] : 0u;
                __syncthreads();
                ss[t] += add;
                __syncthreads();
            }
            u32 S = ss[t];
            u32 Sn = (t < 255u) ? ss[t + 1] : 0u;
            if (S >= KSEL && Sn < KSEL) {
                u32 cum = Sn;
                for (int k = 6; k >= 0; k--) {
                    u32 b = b0 + (u32)k;
                    if (b < NBIN) {
                        u32 c = g_hist[(u32)s*NBINP + b];
                        cum += c;
                        if (cum >= KSEL) { shBin[s] = (int)b; break; }
                    }
                }
            }
        }
        __syncthreads();
    }
    const int b0 = shBin[0], b1 = shBin[1], b2 = shBin[2];
    for (u32 i = blockIdx.x*256u + t; i < TOTAL; i += 65536u) {
        float x; int s; u32 orig;
        cand_addr(i, o13, o26, o52, x, s, orig);
        float obj = 1.f / (1.f + expf(-x));
        if (!(obj > 0.6f)) continue;
        u32 key = __float_as_uint(obj) | 0x80000000u;
        int hidx = (int)((key >> 12) - BINBASE);
        int tb = (s == 0) ? b0 : (s == 1) ? b1 : b2;
        if (hidx > tb) {
            u32 pos = atomicAdd(&g_selCount[s], 1u);
            g_sel[(u32)s*512u + pos] = ((u64)key << 32) | orig;
        } else if (hidx == tb) {
            u32 pos = atomicAdd(&g_poolCount[s], 1u);
            if (pos < POOLCAP)
                g_pool[(u32)s*POOLCAP + pos] = ((u64)key << 32) | (u32)(~orig);
        }
    }
}

// ---------------- K3: threshold-bin top-off + global bitonic sort ----------------
__global__ __launch_bounds__(1024) void k_sortfix() {
    __shared__ u64 sm[SORTCAP];        // 32 KB, reused
    __shared__ u32 sTot[3];
    __shared__ u32 scnt, srank;
    const u32 t = threadIdx.x;
    for (int s = 0; s < 3; s++) {
        u32 direct = g_selCount[s];
        u32 valid  = g_validCount[s];
        u32 need   = (valid >= KSEL) ? (KSEL - direct) : 0u;
        if (t == 0) sTot[s] = direct + need;
        u32 n = g_poolCount[s]; if (n > POOLCAP) n = POOLCAP;
        if (need > 0u) {
            if (n <= (u32)SORTCAP) {
                u32 P = 2u; while (P < n) P <<= 1u;
                for (u32 i = t; i < P; i += 1024u)
                    sm[i] = (i < n) ? g_pool[(u32)s*POOLCAP + i] : 0ull;
                __syncthreads();
                for (u32 k = 2; k <= P; k <<= 1)
                    for (u32 j = k >> 1; j > 0; j >>= 1) {
                        for (u32 i = t; i < P; i += 1024u) {
                            u32 ixj = i ^ j;
                            if (ixj > i) {
                                bool desc = ((i & k) == 0u);
                                u64 x = sm[i], y = sm[ixj];
                                if (desc ? (x < y) : (x > y)) { sm[i] = y; sm[ixj] = x; }
                            }
                        }
                        __syncthreads();
                    }
                for (u32 j = t; j < need; j += 1024u) {
                    u64 v = sm[j];
                    g_sel[(u32)s*512u + direct + j] =
                        (v & 0xFFFFFFFF00000000ull) | (u32)(~(u32)v);
                }
            } else {
                // fallback: exact selection via 64-bit binary search (v unique)
                u64 lo = 1ull, hi = 0xFFFFFFFFFFFFFFFFull;
                while (lo < hi) {
                    u64 mid = lo + ((hi - lo + 1ull) >> 1);
                    if (t == 0) scnt = 0u;
                    __syncthreads();
                    u32 c = 0u;
                    for (u32 j = t; j < n; j += 1024u)
                        if (g_pool[(u32)s*POOLCAP + j] >= mid) c++;
                    if (c) atomicAdd(&scnt, c);
                    __syncthreads();
                    u32 total = scnt;
                    __syncthreads();
                    if (total >= need) lo = mid; else hi = mid - 1ull;
                }
                if (t == 0) srank = 0u;
                __syncthreads();
                for (u32 j = t; j < n; j += 1024u) {
                    u64 v = g_pool[(u32)s*POOLCAP + j];
                    if (v >= lo) {
                        u32 p = atomicAdd(&srank, 1u);
                        if (p < need)
                            g_sel[(u32)s*512u + direct + p] =
                                (v & 0xFFFFFFFF00000000ull) | (u32)(~(u32)v);
                    }
                }
            }
        }
        __syncthreads();
    }
    // ---- global sort: 2048-entry bitonic (score desc, concat-pos asc) ----
    const u32 offc[3] = {0u, OFF1, OFF2};
    for (u32 j = t; j < 2048u; j += 1024u) {
        u64 v = 0ull;
        if (j < (u32)NBOX) {
            u32 s = j >> 9, p = j & 511u;
            if (p < sTot[s]) {
                u64 e = g_sel[s*512u + p];
                u32 key  = (u32)(e >> 32);
                u32 gidx = offc[s] + (u32)e;
                v = ((u64)key << 32) | (u32)(~gidx);
            }
        }
        sm[j] = v;
    }
    __syncthreads();
    for (u32 k = 2; k <= 2048u; k <<= 1)
        for (u32 j = k >> 1; j > 0; j >>= 1) {
            for (u32 i = t; i < 2048u; i += 1024u) {
                u32 ixj = i ^ j;
                if (ixj > i) {
                    bool desc = ((i & k) == 0u);
                    u64 x = sm[i], y = sm[ixj];
                    if (desc ? (x < y) : (x > y)) { sm[i] = y; sm[ixj] = x; }
                }
            }
            __syncthreads();
        }
    for (u32 j = t; j < (u32)NBOX; j += 1024u) g_sorted[j] = sm[j];
}

// ---------------- K4: decode winners (one warp per box) ----------------
__global__ void k_decode(const float* __restrict__ o13, const float* __restrict__ o26,
                         const float* __restrict__ o52,
                         const float* __restrict__ a13, const float* __restrict__ a26,
                         const float* __restrict__ a52) {
    int r = (blockIdx.x * blockDim.x + threadIdx.x) >> 5;
    int lane = threadIdx.x & 31;
    if (r >= NBOX) return;
    u64 e = g_sorted[r];
    u32 key = (u32)(e >> 32);
    if (key == 0u) {
        if (lane == 0) {
            #pragma unroll
            for (int k = 0; k < 9; k++) g_boxes[r*9+k] = 0.f;
            #pragma unroll
            for (int k = 0; k < 5; k++) g_nmsb[r*5+k] = 0.f;
            g_valid[r] = 0;
        }
        return;
    }
    u32 gidx = ~(u32)e;
    const float* p; const float* anc; int H; float ts; u32 loc;
    if (gidx < OFF1)      { p=o13; anc=a13; H=13; ts=32.f; loc=gidx; }
    else if (gidx < OFF2) { p=o26; anc=a26; H=26; ts=16.f; loc=gidx-OFF1; }
    else                  { p=o52; anc=a52; H=52; ts=8.f;  loc=gidx-OFF2; }
    u32 a = loc % 3u; u32 q = loc / 3u;
    u32 w = q % (u32)H; q /= (u32)H;
    u32 h = q % (u32)H; u32 n = q / (u32)H;
    int HW = H*H;
    const float* base = p + (size_t)(n*255u + a*85u)*HW + h*H + w;
    // lanes 1..4 fetch box deltas in parallel with the class loads
    float aux = 0.f;
    if (lane >= 1 && lane <= 4) aux = base[lane * HW];
    float bv = -1e30f; int bc = 1 << 30;       // argmax 80 classes, first-max
    for (int c = lane; c < 80; c += 32) {
        float v = base[(5 + c) * HW];
        if (v > bv) { bv = v; bc = c; }
    }
    #pragma unroll
    for (int off = 16; off; off >>= 1) {
        float ov = __shfl_down_sync(0xffffffffu, bv, off);
        int   oc = __shfl_down_sync(0xffffffffu, bc, off);
        if (ov > bv || (ov == bv && oc < bc)) { bv = ov; bc = oc; }
    }
    float v1 = __shfl_sync(0xffffffffu, aux, 1);
    float v2 = __shfl_sync(0xffffffffu, aux, 2);
    float v3 = __shfl_sync(0xffffffffu, aux, 3);
    float v4 = __shfl_sync(0xffffffffu, aux, 4);
    if (lane == 0) {
        float obj = __uint_as_float(key ^ 0x80000000u);
        float cx = ((float)w + v1) * ts / 416.0f;
        float cy = ((float)h + v2) * ts / 416.0f;
        float bw = anc[a*2+0] * expf(v3) / 416.0f;
        float bh = anc[a*2+1] * expf(v4) / 416.0f;
        float* B = &g_boxes[r*9];
        B[0]=(float)n; B[1]=cx; B[2]=cy; B[3]=bw; B[4]=bh;
        B[5]=obj; B[6]=(float)bc; B[7]=(float)h; B[8]=(float)w;
        float x1 = cx - bw*0.5f, y1 = cy - bh*0.5f;
        float x2 = cx + bw*0.5f, y2 = cy + bh*0.5f;
        float area = fmaxf(x2-x1, 0.f) * fmaxf(y2-y1, 0.f);
        float* Nn = &g_nmsb[r*5];
        Nn[0]=x1; Nn[1]=y1; Nn[2]=x2; Nn[3]=y2; Nn[4]=area;
        g_valid[r] = 1;
    }
}

// ---------------- K5: suppression bitmask (iou inter/min > 0.7, col > row) ----------------
__global__ void k_mask() {
    int cb = blockIdx.x, rb = blockIdx.y;
    __shared__ float c0[64], c1[64], c2[64], c3[64], ca[64];
    int t = threadIdx.x;
    int c = cb*64 + t;
    c0[t]=g_nmsb[c*5+0]; c1[t]=g_nmsb[c*5+1]; c2[t]=g_nmsb[c*5+2];
    c3[t]=g_nmsb[c*5+3]; ca[t]=g_nmsb[c*5+4];
    __syncthreads();
    int r = rb*64 + t;
    float x1=g_nmsb[r*5+0], y1=g_nmsb[r*5+1], x2=g_nmsb[r*5+2],
          y2=g_nmsb[r*5+3], ar=g_nmsb[r*5+4];
    u64 bits = 0ull;
    #pragma unroll 4
    for (int j = 0; j < 64; j++) {
        int cc = cb*64 + j;
        if (cc > r) {
            float ix = fmaxf(fminf(x2, c2[j]) - fmaxf(x1, c0[j]), 0.f);
            float iy = fmaxf(fminf(y2, c3[j]) - fmaxf(y1, c1[j]), 0.f);
            float iou = (ix * iy) / fmaxf(fminf(ar, ca[j]), 1e-9f);
            if (iou > 0.7f) bits |= (1ull << j);
        }
    }
    g_mask[r*NWORD + cb] = bits;
}

// ---------------- K6: greedy scan (sparse chain + predicated fold) ----------------
// Serial closure per 64-box chunk runs over SURVIVING bits only (ffs jump),
// with one lazy LDS of the diagonal word per kept box — no register-array
// spill. Cross-chunk fold is a fully-unrolled predicated OR over 64 pipelined
// LDS per lane (skipped when nothing was kept). Tiles double-buffered.
__global__ __launch_bounds__(256) void k_nms_out(float* __restrict__ out) {
    __shared__ u64 tile[2][64*NWORD];      // 2 x 12 KB
    __shared__ u64 svalidw[NWORD];
    __shared__ u64 skeep[NWORD];
    int tid = threadIdx.x;
    if (tid < NWORD) {
        u64 v = 0ull;
        for (int j = 0; j < 64; j++) if (g_valid[tid*64 + j]) v |= 1ull << j;
        svalidw[tid] = v;
    }
    for (int k = tid; k < 64*NWORD; k += 256)
        tile[0][k] = g_mask[k];
    __syncthreads();
    u64 remv = 0ull;                        // lane w (w<NWORD) holds remv word w
    for (int c = 0; c < NWORD; c++) {
        if (tid >= 32 && c + 1 < NWORD) {   // prefetch next chunk
            for (int k = tid - 32; k < 64*NWORD; k += 224)
                tile[(c+1)&1][k] = g_mask[(size_t)(c+1)*(64*NWORD) + k];
        }
        if (tid < 32) {
            u64* T = tile[c&1];
            u64 cur = __shfl_sync(0xffffffffu, remv, c);
            u64 kept = 0ull;
            if (tid == 0) {
                u64 avail = svalidw[c] & ~cur;   // surviving candidates
                while (avail) {
                    int j = __ffsll((long long)avail) - 1;
                    kept |= 1ull << j;
                    avail &= ~(T[j*NWORD + c] | (1ull << j));
                }
                skeep[c] = kept;
            }
            kept = __shfl_sync(0xffffffffu, kept, 0);
            if (tid < NWORD && kept) {
                u64 acc = 0ull;
                #pragma unroll
                for (int j = 0; j < 64; j++) {
                    u64 m = (u64)0 - ((kept >> j) & 1ull);
                    acc |= T[j*NWORD + tid] & m;
                }
                remv |= acc;
            }
        }
        __syncthreads();
    }
    for (int e = tid; e < NBOX*9; e += 256) {
        int r = e / 9;
        out[e] = g_boxes[e] * (((skeep[r >> 6] >> (r & 63)) & 1ull) ? 1.f : 0.f);
    }
    // ---- re-zero selection state for the next run ----
    for (u32 z = tid; z < 3u*NBINP; z += 256u) g_hist[z] = 0u;
    if (tid < 3) { g_validCount[tid] = 0u; g_selCount[tid] = 0u; g_poolCount[tid] = 0u; }
}

// ---------------- launcher: 6 graph nodes ----------------
extern "C" void kernel_launch(void* const* d_in, const int* in_sizes, int n_in,
                              void* d_out, int out_size) {
    const float* o13 = (const float*)d_in[0];
    const float* o26 = (const float*)d_in[1];
    const float* o52 = (const float*)d_in[2];
    const float* a13 = (const float*)d_in[3];
    const float* a26 = (const float*)d_in[4];
    const float* a52 = (const float*)d_in[5];
    float* out = (float*)d_out;

    k_hist   <<<256, 256>>>(o13, o26, o52);
    k_select <<<256, 256>>>(o13, o26, o52);
    k_sortfix<<<1, 1024>>>();
    k_decode <<<192, 256>>>(o13, o26, o52, a13, a26, a52);
    k_mask   <<<dim3(24,24), 64>>>();
    k_nms_out<<<1, 256>>>(out);
    (void)in_sizes; (void)n_in; (void)out_size;
}

// round 7
// speedup vs baseline: 1.2581x; 1.0362x over previous
#include <cuda_runtime.h>
#include <cstdint>

// ---------------- problem constants ----------------
#define TOTAL   340704u        // 16224 + 64896 + 259584 candidates
#define OFF1    16224u
#define OFF2    81120u
#define KSEL    512u
#define NBOX    1536
#define NWORD   24             // 1536/64 mask words per row
#define BINBASE 0xBF199u       // (bits(0.6)|sign)>>12 ; keys for obj in (0.6,1]
#define NBIN    1640u          // 0xBF800 - 0xBF199 + 1
#define NBINP   1664u          // padded
#define POOLCAP 65536u
#define SORTCAP 4096

typedef unsigned long long u64;
typedef uint32_t u32;

// ---------------- device scratch (static, allocation-free) ----------------
// NOTE: zero-initialized at module load; k_nms_out re-zeroes at the end of
// every run, so every execution starts from zeroed state (deterministic).
__device__ u32   g_hist[3*NBINP];
__device__ u32   g_validCount[3];
__device__ u32   g_selCount[3];
__device__ u32   g_poolCount[3];
__device__ u64   g_sel[3*512];
__device__ u64   g_pool[3*POOLCAP];
__device__ u64   g_sorted[NBOX];
__device__ float g_boxes[NBOX*9];
__device__ float g_nmsb[NBOX*5];     // x1,y1,x2,y2,area
__device__ int   g_valid[NBOX];
__device__ u64   g_mask[NBOX*NWORD];

// ---------------- shared address/key computation ----------------
__device__ __forceinline__ void cand_addr(u32 i,
        const float* __restrict__ o13, const float* __restrict__ o26,
        const float* __restrict__ o52,
        float& x, int& s, u32& orig) {
    if (i < OFF1) {                 // H=13, HW=169, NHW=5408
        u32 loc = i;
        u32 a = loc / 5408u, r = loc - a*5408u;
        u32 n = r / 169u,  hw = r - n*169u;
        x = o13[(n*255u + a*85u)*169u + hw]; s = 0; orig = r*3u + a;
    } else if (i < OFF2) {          // H=26, HW=676, NHW=21632
        u32 loc = i - OFF1;
        u32 a = loc / 21632u, r = loc - a*21632u;
        u32 n = r / 676u,  hw = r - n*676u;
        x = o26[(n*255u + a*85u)*676u + hw]; s = 1; orig = r*3u + a;
    } else {                        // H=52, HW=2704, NHW=86528
        u32 loc = i - OFF2;
        u32 a = loc / 86528u, r = loc - a*86528u;
        u32 n = r / 2704u, hw = r - n*2704u;
        x = o52[(n*255u + a*85u)*2704u + hw]; s = 2; orig = r*3u + a;
    }
}

// ---------------- K1: 1640-bin histogram of score keys ----------------
__global__ __launch_bounds__(256) void k_hist(const float* __restrict__ o13,
                                              const float* __restrict__ o26,
                                              const float* __restrict__ o52) {
    __shared__ u32 sh[3*NBINP];
    __shared__ u32 svc[3];
    for (u32 b = threadIdx.x; b < 3u*NBINP; b += 256u) sh[b] = 0u;
    if (threadIdx.x < 3u) svc[threadIdx.x] = 0u;
    __syncthreads();
    for (u32 i = blockIdx.x*256u + threadIdx.x; i < TOTAL; i += 65536u) {
        float x; int s; u32 orig;
        cand_addr(i, o13, o26, o52, x, s, orig);
        float obj = 1.f / (1.f + expf(-x));
        if (obj > 0.6f) {
            u32 key = __float_as_uint(obj) | 0x80000000u;
            atomicAdd(&sh[(u32)s*NBINP + ((key >> 12) - BINBASE)], 1u);
            atomicAdd(&svc[s], 1u);
        }
    }
    __syncthreads();
    for (u32 b = threadIdx.x; b < 3u*NBINP; b += 256u) {
        u32 v = sh[b];
        if (v) atomicAdd(&g_hist[b], v);
    }
    if (threadIdx.x < 3u && svc[threadIdx.x]) atomicAdd(&g_validCount[threadIdx.x], svc[threadIdx.x]);
}

// ---------------- K2: recompute keys; direct-select above threshold bin,
//                  pool the threshold bin. ----
__global__ __launch_bounds__(256) void k_select(const float* __restrict__ o13,
                                                const float* __restrict__ o26,
                                                const float* __restrict__ o52) {
    __shared__ u32 ss[256];
    __shared__ int shBin[3];
    const u32 t = threadIdx.x;
    // per-scale threshold-bin scan (block-redundant, uniform branches)
    for (int s = 0; s < 3; s++) {
        if (g_validCount[s] < KSEL) {
            if (t == 0) shBin[s] = -2;            // select every valid directly
        } else {
            u32 b0 = t * 7u;
            u32 part = 0u;
            #pragma unroll
            for (u32 k = 0; k < 7u; k++) {
                u32 b = b0 + k;
                if (b < NBIN) part += g_hist[(u32)s*NBINP + b];
            }
            ss[t] = part;
            __syncthreads();
            for (u32 off = 1; off < 256u; off <<= 1) {   // inclusive suffix scan
                u32 add = (t + off < 256u) ? ss[t + off] : 0u;
                __syncthreads();
                ss[t] += add;
                __syncthreads();
            }
            u32 S = ss[t];
            u32 Sn = (t < 255u) ? ss[t + 1] : 0u;
            if (S >= KSEL && Sn < KSEL) {
                u32 cum = Sn;
                for (int k = 6; k >= 0; k--) {
                    u32 b = b0 + (u32)k;
                    if (b < NBIN) {
                        u32 c = g_hist[(u32)s*NBINP + b];
                        cum += c;
                        if (cum >= KSEL) { shBin[s] = (int)b; break; }
                    }
                }
            }
        }
        __syncthreads();
    }
    const int b0 = shBin[0], b1 = shBin[1], b2 = shBin[2];
    for (u32 i = blockIdx.x*256u + t; i < TOTAL; i += 65536u) {
        float x; int s; u32 orig;
        cand_addr(i, o13, o26, o52, x, s, orig);
        float obj = 1.f / (1.f + expf(-x));
        if (!(obj > 0.6f)) continue;
        u32 key = __float_as_uint(obj) | 0x80000000u;
        int hidx = (int)((key >> 12) - BINBASE);
        int tb = (s == 0) ? b0 : (s == 1) ? b1 : b2;
        if (hidx > tb) {
            u32 pos = atomicAdd(&g_selCount[s], 1u);
            g_sel[(u32)s*512u + pos] = ((u64)key << 32) | orig;
        } else if (hidx == tb) {
            u32 pos = atomicAdd(&g_poolCount[s], 1u);
            if (pos < POOLCAP)
                g_pool[(u32)s*POOLCAP + pos] = ((u64)key << 32) | (u32)(~orig);
        }
    }
}

// ---------------- K3: threshold-bin top-off + global bitonic sort ----------------
__global__ __launch_bounds__(1024) void k_sortfix() {
    __shared__ u64 sm[SORTCAP];        // 32 KB, reused
    __shared__ u32 sTot[3];
    __shared__ u32 scnt, srank;
    const u32 t = threadIdx.x;
    for (int s = 0; s < 3; s++) {
        u32 direct = g_selCount[s];
        u32 valid  = g_validCount[s];
        u32 need   = (valid >= KSEL) ? (KSEL - direct) : 0u;
        if (t == 0) sTot[s] = direct + need;
        u32 n = g_poolCount[s]; if (n > POOLCAP) n = POOLCAP;
        if (need > 0u) {
            if (n <= (u32)SORTCAP) {
                u32 P = 2u; while (P < n) P <<= 1u;
                for (u32 i = t; i < P; i += 1024u)
                    sm[i] = (i < n) ? g_pool[(u32)s*POOLCAP + i] : 0ull;
                __syncthreads();
                for (u32 k = 2; k <= P; k <<= 1)
                    for (u32 j = k >> 1; j > 0; j >>= 1) {
                        for (u32 i = t; i < P; i += 1024u) {
                            u32 ixj = i ^ j;
                            if (ixj > i) {
                                bool desc = ((i & k) == 0u);
                                u64 x = sm[i], y = sm[ixj];
                                if (desc ? (x < y) : (x > y)) { sm[i] = y; sm[ixj] = x; }
                            }
                        }
                        __syncthreads();
                    }
                for (u32 j = t; j < need; j += 1024u) {
                    u64 v = sm[j];
                    g_sel[(u32)s*512u + direct + j] =
                        (v & 0xFFFFFFFF00000000ull) | (u32)(~(u32)v);
                }
            } else {
                // fallback: exact selection via 64-bit binary search (v unique)
                u64 lo = 1ull, hi = 0xFFFFFFFFFFFFFFFFull;
                while (lo < hi) {
                    u64 mid = lo + ((hi - lo + 1ull) >> 1);
                    if (t == 0) scnt = 0u;
                    __syncthreads();
                    u32 c = 0u;
                    for (u32 j = t; j < n; j += 1024u)
                        if (g_pool[(u32)s*POOLCAP + j] >= mid) c++;
                    if (c) atomicAdd(&scnt, c);
                    __syncthreads();
                    u32 total = scnt;
                    __syncthreads();
                    if (total >= need) lo = mid; else hi = mid - 1ull;
                }
                if (t == 0) srank = 0u;
                __syncthreads();
                for (u32 j = t; j < n; j += 1024u) {
                    u64 v = g_pool[(u32)s*POOLCAP + j];
                    if (v >= lo) {
                        u32 p = atomicAdd(&srank, 1u);
                        if (p < need)
                            g_sel[(u32)s*512u + direct + p] =
                                (v & 0xFFFFFFFF00000000ull) | (u32)(~(u32)v);
                    }
                }
            }
        }
        __syncthreads();
    }
    // ---- global sort: 2048-entry bitonic (score desc, concat-pos asc) ----
    const u32 offc[3] = {0u, OFF1, OFF2};
    for (u32 j = t; j < 2048u; j += 1024u) {
        u64 v = 0ull;
        if (j < (u32)NBOX) {
            u32 s = j >> 9, p = j & 511u;
            if (p < sTot[s]) {
                u64 e = g_sel[s*512u + p];
                u32 key  = (u32)(e >> 32);
                u32 gidx = offc[s] + (u32)e;
                v = ((u64)key << 32) | (u32)(~gidx);
            }
        }
        sm[j] = v;
    }
    __syncthreads();
    for (u32 k = 2; k <= 2048u; k <<= 1)
        for (u32 j = k >> 1; j > 0; j >>= 1) {
            for (u32 i = t; i < 2048u; i += 1024u) {
                u32 ixj = i ^ j;
                if (ixj > i) {
                    bool desc = ((i & k) == 0u);
                    u64 x = sm[i], y = sm[ixj];
                    if (desc ? (x < y) : (x > y)) { sm[i] = y; sm[ixj] = x; }
                }
            }
            __syncthreads();
        }
    for (u32 j = t; j < (u32)NBOX; j += 1024u) g_sorted[j] = sm[j];
}

// ---------------- K4: decode winners (one warp per box) ----------------
__global__ void k_decode(const float* __restrict__ o13, const float* __restrict__ o26,
                         const float* __restrict__ o52,
                         const float* __restrict__ a13, const float* __restrict__ a26,
                         const float* __restrict__ a52) {
    int r = (blockIdx.x * blockDim.x + threadIdx.x) >> 5;
    int lane = threadIdx.x & 31;
    if (r >= NBOX) return;
    u64 e = g_sorted[r];
    u32 key = (u32)(e >> 32);
    if (key == 0u) {
        if (lane == 0) {
            #pragma unroll
            for (int k = 0; k < 9; k++) g_boxes[r*9+k] = 0.f;
            #pragma unroll
            for (int k = 0; k < 5; k++) g_nmsb[r*5+k] = 0.f;
            g_valid[r] = 0;
        }
        return;
    }
    u32 gidx = ~(u32)e;
    const float* p; const float* anc; int H; float ts; u32 loc;
    if (gidx < OFF1)      { p=o13; anc=a13; H=13; ts=32.f; loc=gidx; }
    else if (gidx < OFF2) { p=o26; anc=a26; H=26; ts=16.f; loc=gidx-OFF1; }
    else                  { p=o52; anc=a52; H=52; ts=8.f;  loc=gidx-OFF2; }
    u32 a = loc % 3u; u32 q = loc / 3u;
    u32 w = q % (u32)H; q /= (u32)H;
    u32 h = q % (u32)H; u32 n = q / (u32)H;
    int HW = H*H;
    const float* base = p + (size_t)(n*255u + a*85u)*HW + h*H + w;
    // lanes 1..4 fetch box deltas in parallel with the class loads
    float aux = 0.f;
    if (lane >= 1 && lane <= 4) aux = base[lane * HW];
    float bv = -1e30f; int bc = 1 << 30;       // argmax 80 classes, first-max
    for (int c = lane; c < 80; c += 32) {
        float v = base[(5 + c) * HW];
        if (v > bv) { bv = v; bc = c; }
    }
    #pragma unroll
    for (int off = 16; off; off >>= 1) {
        float ov = __shfl_down_sync(0xffffffffu, bv, off);
        int   oc = __shfl_down_sync(0xffffffffu, bc, off);
        if (ov > bv || (ov == bv && oc < bc)) { bv = ov; bc = oc; }
    }
    float v1 = __shfl_sync(0xffffffffu, aux, 1);
    float v2 = __shfl_sync(0xffffffffu, aux, 2);
    float v3 = __shfl_sync(0xffffffffu, aux, 3);
    float v4 = __shfl_sync(0xffffffffu, aux, 4);
    if (lane == 0) {
        float obj = __uint_as_float(key ^ 0x80000000u);
        float cx = ((float)w + v1) * ts / 416.0f;
        float cy = ((float)h + v2) * ts / 416.0f;
        float bw = anc[a*2+0] * expf(v3) / 416.0f;
        float bh = anc[a*2+1] * expf(v4) / 416.0f;
        float* B = &g_boxes[r*9];
        B[0]=(float)n; B[1]=cx; B[2]=cy; B[3]=bw; B[4]=bh;
        B[5]=obj; B[6]=(float)bc; B[7]=(float)h; B[8]=(float)w;
        float x1 = cx - bw*0.5f, y1 = cy - bh*0.5f;
        float x2 = cx + bw*0.5f, y2 = cy + bh*0.5f;
        float area = fmaxf(x2-x1, 0.f) * fmaxf(y2-y1, 0.f);
        float* Nn = &g_nmsb[r*5];
        Nn[0]=x1; Nn[1]=y1; Nn[2]=x2; Nn[3]=y2; Nn[4]=area;
        g_valid[r] = 1;
    }
}

// ---------------- K5: suppression bitmask (iou inter/min > 0.7, col > row) ----------------
__global__ void k_mask() {
    int cb = blockIdx.x, rb = blockIdx.y;
    __shared__ float c0[64], c1[64], c2[64], c3[64], ca[64];
    int t = threadIdx.x;
    int c = cb*64 + t;
    c0[t]=g_nmsb[c*5+0]; c1[t]=g_nmsb[c*5+1]; c2[t]=g_nmsb[c*5+2];
    c3[t]=g_nmsb[c*5+3]; ca[t]=g_nmsb[c*5+4];
    __syncthreads();
    int r = rb*64 + t;
    float x1=g_nmsb[r*5+0], y1=g_nmsb[r*5+1], x2=g_nmsb[r*5+2],
          y2=g_nmsb[r*5+3], ar=g_nmsb[r*5+4];
    u64 bits = 0ull;
    #pragma unroll 4
    for (int j = 0; j < 64; j++) {
        int cc = cb*64 + j;
        if (cc > r) {
            float ix = fmaxf(fminf(x2, c2[j]) - fmaxf(x1, c0[j]), 0.f);
            float iy = fmaxf(fminf(y2, c3[j]) - fmaxf(y1, c1[j]), 0.f);
            float iou = (ix * iy) / fmaxf(fminf(ar, ca[j]), 1e-9f);
            if (iou > 0.7f) bits |= (1ull << j);
        }
    }
    g_mask[r*NWORD + cb] = bits;
}

// ---------------- K6: greedy scan — NAMED-REGISTER ALU closure ----------------
// Thread 0 holds the 64 diagonal words of the current chunk in 128 named u32
// registers (static indices — no spill) so each greedy step is a ~16-cycle
// shift/sar/and chain instead of a dependent LDS. Early exit every 8 steps.
#define ROWS8(M,a,b,c2,d,e,f,g,h) M(a) M(b) M(c2) M(d) M(e) M(f) M(g) M(h)
#define DECLR(j)  u32 rlo##j, rhi##j;
#define LOADR(j)  { u64 v_ = T[(j)*NWORD + c]; rlo##j = (u32)v_; rhi##j = (u32)(v_ >> 32); }
#define STEPL(j)  { u32 m_ = (u32)(((int)(alo << (31-(j)))) >> 31); \
                    klo |= alo & (1u<<(j)); \
                    alo &= ~(rlo##j & m_); ahi &= ~(rhi##j & m_); }
#define STEPH(j)  { u32 m_ = (u32)(((int)(ahi << (63-(j)))) >> 31); \
                    khi |= ahi & (1u<<((j)-32)); \
                    ahi &= ~(rhi##j & m_); }

__global__ __launch_bounds__(256, 1) void k_nms_out(float* __restrict__ out) {
    __shared__ u64 tile[2][64*NWORD];      // 2 x 12 KB
    __shared__ u64 svalidw[NWORD];
    __shared__ u64 skeep[NWORD];
    int tid = threadIdx.x;
    if (tid < NWORD) {
        u64 v = 0ull;
        for (int j = 0; j < 64; j++) if (g_valid[tid*64 + j]) v |= 1ull << j;
        svalidw[tid] = v;
    }
    for (int k = tid; k < 64*NWORD; k += 256)
        tile[0][k] = g_mask[k];
    __syncthreads();
    u64 remv = 0ull;                        // lane w (w<NWORD) holds remv word w
    for (int c = 0; c < NWORD; c++) {
        if (tid >= 32 && c + 1 < NWORD) {   // prefetch next chunk
            for (int k = tid - 32; k < 64*NWORD; k += 224)
                tile[(c+1)&1][k] = g_mask[(size_t)(c+1)*(64*NWORD) + k];
        }
        if (tid < 32) {
            u64* T = tile[c&1];
            u64 cur = __shfl_sync(0xffffffffu, remv, c);
            u64 kept = 0ull;
            if (tid == 0) {
                u64 avail64 = svalidw[c] & ~cur;   // surviving candidates
                u32 alo = (u32)avail64, ahi = (u32)(avail64 >> 32);
                u32 klo = 0u, khi = 0u;
                ROWS8(DECLR, 0, 1, 2, 3, 4, 5, 6, 7)
                ROWS8(DECLR, 8, 9,10,11,12,13,14,15)
                ROWS8(DECLR,16,17,18,19,20,21,22,23)
                ROWS8(DECLR,24,25,26,27,28,29,30,31)
                ROWS8(DECLR,32,33,34,35,36,37,38,39)
                ROWS8(DECLR,40,41,42,43,44,45,46,47)
                ROWS8(DECLR,48,49,50,51,52,53,54,55)
                ROWS8(DECLR,56,57,58,59,60,61,62,63)
                ROWS8(LOADR, 0, 1, 2, 3, 4, 5, 6, 7)
                ROWS8(LOADR, 8, 9,10,11,12,13,14,15)
                ROWS8(LOADR,16,17,18,19,20,21,22,23)
                ROWS8(LOADR,24,25,26,27,28,29,30,31)
                ROWS8(LOADR,32,33,34,35,36,37,38,39)
                ROWS8(LOADR,40,41,42,43,44,45,46,47)
                ROWS8(LOADR,48,49,50,51,52,53,54,55)
                ROWS8(LOADR,56,57,58,59,60,61,62,63)
                do {
                    ROWS8(STEPL, 0, 1, 2, 3, 4, 5, 6, 7)
                    if (!(alo | ahi)) break;
                    ROWS8(STEPL, 8, 9,10,11,12,13,14,15)
                    if (!(alo | ahi)) break;
                    ROWS8(STEPL,16,17,18,19,20,21,22,23)
                    if (!(alo | ahi)) break;
                    ROWS8(STEPL,24,25,26,27,28,29,30,31)
                    if (!ahi) break;
                    ROWS8(STEPH,32,33,34,35,36,37,38,39)
                    if (!ahi) break;
                    ROWS8(STEPH,40,41,42,43,44,45,46,47)
                    if (!ahi) break;
                    ROWS8(STEPH,48,49,50,51,52,53,54,55)
                    if (!ahi) break;
                    ROWS8(STEPH,56,57,58,59,60,61,62,63)
                } while (0);
                kept = (u64)klo | ((u64)khi << 32);
                skeep[c] = kept;
            }
            kept = __shfl_sync(0xffffffffu, kept, 0);
            if (tid < NWORD && kept) {
                u64 acc = 0ull;
                #pragma unroll
                for (int j = 0; j < 64; j++) {
                    u64 m = (u64)0 - ((kept >> j) & 1ull);
                    acc |= T[j*NWORD + tid] & m;
                }
                remv |= acc;
            }
        }
        __syncthreads();
    }
    for (int e = tid; e < NBOX*9; e += 256) {
        int r = e / 9;
        out[e] = g_boxes[e] * (((skeep[r >> 6] >> (r & 63)) & 1ull) ? 1.f : 0.f);
    }
    // ---- re-zero selection state for the next run ----
    for (u32 z = tid; z < 3u*NBINP; z += 256u) g_hist[z] = 0u;
    if (tid < 3) { g_validCount[tid] = 0u; g_selCount[tid] = 0u; g_poolCount[tid] = 0u; }
}

// ---------------- launcher: 6 graph nodes ----------------
extern "C" void kernel_launch(void* const* d_in, const int* in_sizes, int n_in,
                              void* d_out, int out_size) {
    const float* o13 = (const float*)d_in[0];
    const float* o26 = (const float*)d_in[1];
    const float* o52 = (const float*)d_in[2];
    const float* a13 = (const float*)d_in[3];
    const float* a26 = (const float*)d_in[4];
    const float* a52 = (const float*)d_in[5];
    float* out = (float*)d_out;

    k_hist   <<<256, 256>>>(o13, o26, o52);
    k_select <<<256, 256>>>(o13, o26, o52);
    k_sortfix<<<1, 1024>>>();
    k_decode <<<192, 256>>>(o13, o26, o52, a13, a26, a52);
    k_mask   <<<dim3(24,24), 64>>>();
    k_nms_out<<<1, 256>>>(out);
    (void)in_sizes; (void)n_in; (void)out_size;
}